// round 3
// baseline (speedup 1.0000x reference)
#include <cuda_runtime.h>
#include <cstdint>

// ---------------------------------------------------------------------------
// Problem: block-diagonal linear, irreps 256x0e + 256x1o + 256x2e.
// Reformulated per block b as GEMM over rows (z,i):  M_b = B*d_b, N=256, K=256
//   A'[z*d+i][u] = feat[z, xoff_b + u*d + i]   (contiguous k-chunks per z!)
//   C = A' * W_b / 16,  scattered back with the same (z,i) mapping.
// Legacy mma.sync m16n8k8 tf32 (tcgen05 unavailable: PTX targets compute_103).
// ---------------------------------------------------------------------------
#define HX_B    50000
#define HX_FEAT 2304

static constexpr int TM = 128;        // rows per CTA tile
static constexpr int TN = 256;        // full N per CTA
static constexpr int KC = 32;         // k-chunk
static constexpr int NCHUNK = 256 / KC;
static constexpr int NTHREADS = 512;  // 16 warps: 4 (M) x 4 (N)

// tiles per block:  ceil(50000/128)=391, ceil(150000/128)=1172, ceil(250000/128)=1954
static constexpr int T0 = 391, T1 = 391 + 1172, T2 = 391 + 1172 + 1954; // 3517

// smem (floats): A tiles padded stride 36 (conflict-free frag+stage),
// B stored [k][n] stride 264 (8t+g distinct banks; contiguous stage stores)
static constexpr int SA = 36;
static constexpr int SB = 264;
static constexpr int A_BUF = TM * SA;             // 4608 floats
static constexpr int B_BUF = KC * SB;             // 8448 floats
static constexpr int OFF_A0 = 0;
static constexpr int OFF_A1 = A_BUF;
static constexpr int OFF_B0 = 2 * A_BUF;
static constexpr int OFF_B1 = 2 * A_BUF + B_BUF;
static constexpr int SM_BYTES = (2 * A_BUF + 2 * B_BUF) * 4;   // 104448

// ---------------------------------------------------------------------------
__device__ __forceinline__ uint32_t smem_u32(const void* p) {
    uint32_t a;
    asm("{ .reg .u64 t; cvta.to.shared.u64 t, %1; cvt.u32.u64 %0, t; }"
        : "=r"(a) : "l"(p));
    return a;
}

__device__ __forceinline__ uint32_t f2tf(float x) {
    uint32_t r;
    asm("cvt.rna.tf32.f32 %0, %1;" : "=r"(r) : "f"(x));
    return r;
}

__device__ __forceinline__ void mma8(float* c, const uint32_t* a,
                                     uint32_t b0, uint32_t b1) {
    asm volatile(
        "mma.sync.aligned.m16n8k8.row.col.f32.tf32.tf32.f32 "
        "{%0,%1,%2,%3}, {%4,%5,%6,%7}, {%8,%9}, {%0,%1,%2,%3};"
        : "+f"(c[0]), "+f"(c[1]), "+f"(c[2]), "+f"(c[3])
        : "r"(a[0]), "r"(a[1]), "r"(a[2]), "r"(a[3]), "r"(b0), "r"(b1));
}

#define CP_ASYNC4(dst, src, sz)                                          \
    asm volatile("cp.async.ca.shared.global [%0], [%1], 4, %2;"          \
                 :: "r"(dst), "l"(src), "r"(sz) : "memory")
#define CP_ASYNC16(dst, src)                                             \
    asm volatile("cp.async.cg.shared.global [%0], [%1], 16;"             \
                 :: "r"(dst), "l"(src) : "memory")
#define CP_COMMIT() asm volatile("cp.async.commit_group;" ::: "memory")
#define CP_WAIT(n)  asm volatile("cp.async.wait_group %0;" :: "n"(n) : "memory")

// ---------------------------------------------------------------------------
__global__ void __launch_bounds__(NTHREADS, 1)
linear_mma_kernel(const float* __restrict__ feat,
                  const float* __restrict__ wt,
                  float* __restrict__ out)
{
    extern __shared__ float sm[];
    const uint32_t smb = smem_u32(sm);

    const int tid  = threadIdx.x;
    const int wid  = tid >> 5;
    const int lane = tid & 31;
    const int g    = lane >> 2;   // groupID
    const int tg   = lane & 3;    // threadID_in_group
    const int wm   = wid & 3;     // warp M index (rows wm*32 .. +31)
    const int wn   = wid >> 2;    // warp N index (cols wn*64 .. +63)

    // ---- block / tile decode ----
    const int bid = blockIdx.x;
    int d, xoff, woff, Mtot, m0;
    if (bid < T0)      { d = 1; xoff = 0;    woff = 0;      Mtot = 50000;  m0 = bid * TM; }
    else if (bid < T1) { d = 3; xoff = 256;  woff = 65536;  Mtot = 150000; m0 = (bid - T0) * TM; }
    else               { d = 5; xoff = 1024; woff = 131072; Mtot = 250000; m0 = (bid - T1) * TM; }

    const float* wblk = wt + woff;

    // ---- per-thread A staging bases (8 rows each): byte offset into feat, or ~0 ----
    uint32_t abase[8];
    {
        const int r0 = tid >> 5;
        #pragma unroll
        for (int j = 0; j < 8; j++) {
            const int rg = m0 + r0 + 16 * j;
            if (rg < Mtot) {
                const int z = rg / d, i = rg % d;
                abase[j] = (uint32_t)((z * HX_FEAT + xoff + i) * 4);
            } else {
                abase[j] = 0xFFFFFFFFu;
            }
        }
    }

    // ---- staging lambda-ish (macro via inline) ----
    auto stage = [&](int u0, uint32_t aoff, uint32_t boff) {
        // A: lane = k, rows r0 + 16j
        const int k = lane;
        const int r0 = tid >> 5;
        #pragma unroll
        for (int j = 0; j < 8; j++) {
            const uint32_t dst = smb + (aoff + (uint32_t)(r0 + 16 * j) * SA + k) * 4;
            const uint32_t off = abase[j];
            const int sz = (off == 0xFFFFFFFFu) ? 0 : 4;
            const char* src = (const char*)feat +
                (sz ? (off + (uint32_t)((u0 + k) * d) * 4) : 0u);
            CP_ASYNC4(dst, src, sz);
        }
        // B = W[u0+k][n], [k][n] layout, float4 along n
        #pragma unroll
        for (int p = 0; p < 4; p++) {
            const int idx = tid + p * NTHREADS;       // 0..2047
            const int kk = idx >> 6;                  // 0..31
            const int nn = (idx & 63) * 4;            // 0..252
            const uint32_t dst = smb + (boff + (uint32_t)kk * SB + nn) * 4;
            const float* src = wblk + (size_t)(u0 + kk) * 256 + nn;
            CP_ASYNC16(dst, src);
        }
        CP_COMMIT();
    };

    // ---- accumulators ----
    float c[2][8][4];
    #pragma unroll
    for (int mf = 0; mf < 2; mf++)
        #pragma unroll
        for (int nf = 0; nf < 8; nf++)
            #pragma unroll
            for (int q = 0; q < 4; q++) c[mf][nf][q] = 0.0f;

    // ---- pipeline: prefetch chunk 0 ----
    stage(0, OFF_A0, OFF_B0);

    #pragma unroll 1
    for (int ch = 0; ch < NCHUNK; ch++) {
        const uint32_t aoff = (ch & 1) ? OFF_A1 : OFF_A0;
        const uint32_t boff = (ch & 1) ? OFF_B1 : OFF_B0;

        if (ch + 1 < NCHUNK) {
            stage((ch + 1) * KC,
                  (ch & 1) ? OFF_A0 : OFF_A1,
                  (ch & 1) ? OFF_B0 : OFF_B1);
            CP_WAIT(1);
        } else {
            CP_WAIT(0);
        }
        __syncthreads();

        const float* Abuf = sm + aoff;
        const float* Bbuf = sm + boff;
        #pragma unroll
        for (int s = 0; s < 4; s++) {
            const int kb = 8 * s;
            uint32_t a[2][4];
            #pragma unroll
            for (int mf = 0; mf < 2; mf++) {
                const int row = wm * 32 + mf * 16 + g;
                a[mf][0] = f2tf(Abuf[row * SA + kb + tg]);
                a[mf][1] = f2tf(Abuf[(row + 8) * SA + kb + tg]);
                a[mf][2] = f2tf(Abuf[row * SA + kb + tg + 4]);
                a[mf][3] = f2tf(Abuf[(row + 8) * SA + kb + tg + 4]);
            }
            #pragma unroll
            for (int nf = 0; nf < 8; nf++) {
                const int col = wn * 64 + nf * 8 + g;
                const uint32_t b0 = f2tf(Bbuf[(kb + tg) * SB + col]);
                const uint32_t b1 = f2tf(Bbuf[(kb + tg + 4) * SB + col]);
                mma8(c[0][nf], a[0], b0, b1);
                mma8(c[1][nf], a[1], b0, b1);
            }
        }
        __syncthreads();
    }

    // ---- epilogue: scatter C back as (z,i) rows, scale 1/sqrt(256) ----
    const float SCALE = 0.0625f;
    #pragma unroll
    for (int mf = 0; mf < 2; mf++) {
        const int row_lo = wm * 32 + mf * 16 + g;
        #pragma unroll
        for (int rr = 0; rr < 2; rr++) {
            const int rg = m0 + row_lo + rr * 8;
            if (rg < Mtot) {
                const int z = rg / d, i = rg % d;
                float* op = out + (size_t)z * HX_FEAT + xoff + i;
                #pragma unroll
                for (int nf = 0; nf < 8; nf++) {
                    const int n0 = wn * 64 + nf * 8 + 2 * tg;
                    op[(size_t)n0 * d]       = c[mf][nf][rr * 2 + 0] * SCALE;
                    op[(size_t)(n0 + 1) * d] = c[mf][nf][rr * 2 + 1] * SCALE;
                }
            }
        }
    }
}

// ---------------------------------------------------------------------------
extern "C" void kernel_launch(void* const* d_in, const int* in_sizes, int n_in,
                              void* d_out, int out_size) {
    const float* feat = (const float*)d_in[0];
    const float* wt   = (const float*)d_in[1];
    float* out        = (float*)d_out;

    cudaFuncSetAttribute(linear_mma_kernel,
                         cudaFuncAttributeMaxDynamicSharedMemorySize, SM_BYTES);

    linear_mma_kernel<<<T2, NTHREADS, SM_BYTES>>>(feat, wt, out);
}